// round 12
// baseline (speedup 1.0000x reference)
#include <cuda_runtime.h>

// CRF mean log-likelihood, B=1024, S=1024, T=32.
// Inputs (metadata order): emissions f32 [B,S,T], tags i32 [B,S], mask [B,S]
// (dtype probed at runtime), start f32 [T], transitions f32 [T,T], end f32 [T].
// Output: 1 float.
//
// One warp per batch runs BOTH half-chains (forward head->mid with E, backward
// tail->mid with E^T) interleaved for in-warp ILP. Register-resident scaled
// recursion; 4-way t-quarter-split matvec via shfl; exact power-of-2
// normalization every 2 steps (pend/Kacc); warp-local combine at mid.

#define BATCH   1024
#define SLEN    1024
#define TT      32
#define BPB     7
#define THREADS (BPB * 32)               // 224
#define NBLK    ((BATCH + BPB - 1) / BPB)  // 147 -> one wave
#define FULLM   0xffffffffu

__device__ double   g_contrib[BATCH];
__device__ double   g_cnt[BATCH];
__device__ unsigned g_sem = 0;

__device__ __forceinline__ float ex2f_(float x) { float r; asm("ex2.approx.f32 %0, %1;" : "=f"(r) : "f"(x)); return r; }
__device__ __forceinline__ unsigned long long pk2(float lo, float hi) {
    unsigned long long r; asm("mov.b64 %0, {%1, %2};" : "=l"(r) : "f"(lo), "f"(hi)); return r;
}
__device__ __forceinline__ void fma2(unsigned long long& d, unsigned long long a, unsigned long long b) {
    asm("fma.rn.f32x2 %0, %1, %2, %0;" : "+l"(d) : "l"(a), "l"(b));
}
__device__ __forceinline__ void add2(unsigned long long& d, unsigned long long a, unsigned long long b) {
    asm("add.rn.f32x2 %0, %1, %2;" : "=l"(d) : "l"(a), "l"(b));
}
__device__ __forceinline__ void upk(unsigned long long v, float& x, float& y) {
    asm("mov.b64 {%0, %1}, %2;" : "=f"(x), "=f"(y) : "l"(v));
}

// Probe mask dtype from its first bytes (mask[0]=mask[1]=true since len>=256).
__device__ __forceinline__ int probe_mask_mode(const void* m) {
    const unsigned char* u = (const unsigned char*)m;
    if (u[0] != 0 && u[1] != 0) return 0;           // u8 / bool
    if (u[0] == 0) return (u[3] != 0) ? 2 : 4;      // f32 : f64
    return (u[4] != 0) ? 1 : 3;                     // i32 : i64
}
__device__ __forceinline__ bool mask_at(const void* m, int mode, size_t k) {
    switch (mode) {
        case 0:  return ((const unsigned char*)m)[k] != 0;
        case 1:  return ((const int*)m)[k] != 0;
        case 2:  return ((const float*)m)[k] != 0.0f;
        default: { const int* p = (const int*)m; return (p[2*k] | p[2*k+1]) != 0; } // 64-bit
    }
}

// Quarter-split matvec: lane returns its column's full dot.
__device__ __forceinline__ float dotq(float pcur, int qbase,
                                      const unsigned long long* __restrict__ E2a,
                                      const unsigned long long* __restrict__ E2b)
{
    float bb[8];
    #pragma unroll
    for (int i = 0; i < 8; i++) bb[i] = __shfl_sync(FULLM, pcur, qbase + i);

    unsigned long long ra0 = 0ull, ra1 = 0ull, rb0 = 0ull, rb1 = 0ull;
    #pragma unroll
    for (int i = 0; i < 8; i += 2) {
        unsigned long long bp0 = pk2(bb[i],     bb[i]);
        unsigned long long bp1 = pk2(bb[i + 1], bb[i + 1]);
        fma2(ra0, bp0, E2a[i]);     fma2(rb0, bp0, E2b[i]);
        fma2(ra1, bp1, E2a[i + 1]); fma2(rb1, bp1, E2b[i + 1]);
    }
    add2(ra0, ra0, ra1);
    add2(rb0, rb0, rb1);
    float r0, r1, r2, r3;
    upk(ra0, r0, r1);
    upk(rb0, r2, r3);
    float a0  = r0 + __shfl_xor_sync(FULLM, r1, 8);
    float a2  = r2 + __shfl_xor_sync(FULLM, r3, 8);
    return a0 + __shfl_xor_sync(FULLM, a2, 16);
}

__device__ __forceinline__ void extract_scale(float p, int& Kacc, int& pend, float& sc)
{
    float p0 = __shfl_sync(FULLM, p, 0);
    int e = __float_as_int(p0) >> 23;
    Kacc += pend; pend = e - 127;
    sc = __int_as_float((254 - e) << 23);
}

__global__ void __launch_bounds__(THREADS)
crf_fused_kernel(const float* __restrict__ em,
                 const int* __restrict__ tags,
                 const void* __restrict__ maskp,
                 const float* __restrict__ startv,
                 const float* __restrict__ transv,
                 const float* __restrict__ endv,
                 float* __restrict__ out)
{
    __shared__ float s_trans[TT * TT];
    __shared__ float s_start[TT];
    __shared__ float s_end[TT];
    __shared__ double s_r1[BPB], s_r2[BPB];
    __shared__ bool   s_last;

    const int tid   = threadIdx.x;
    const int w     = tid >> 5;
    const int lane  = tid & 31;
    const int b     = blockIdx.x * BPB + w;
    const int qbase = (lane >> 3) << 3;

    for (int i = tid; i < TT * TT; i += THREADS) s_trans[i] = transv[i];
    if (tid < TT) { s_start[tid] = startv[tid]; s_end[tid] = endv[tid]; }
    __syncthreads();

    const float L2E = 1.4426950408889634f;

    int head = 0, tail = -1, len = 0;
    if (b < BATCH) {
        const int mmode = probe_mask_mode(maskp);
        const size_t mbase = (size_t)b * SLEN;
        int h = -1;
        #pragma unroll 4
        for (int i = 0; i < SLEN / 32; i++) {
            bool mv = mask_at(maskp, mmode, mbase + i * 32 + lane);
            unsigned bits = __ballot_sync(FULLM, mv);
            len += __popc(bits);
            if (bits) {
                if (h < 0) h = i * 32 + (__ffs(bits) - 1);
                tail = i * 32 + 31 - __clz(bits);
            }
        }
        head = (h < 0) ? 0 : h;
    }

    if (b < BATCH) {
        if (len > 0) {
            const float* emb = em + (size_t)b * SLEN * TT;
            const int*   tg  = tags + (size_t)b * SLEN;
            const int    mid = (head + tail) >> 1;
            const bool   hasB = (tail > mid);

            // ---- numerator: gold-path score, fp64, whole range ----
            double nsum = 0.0;
            for (int j = head + 1 + lane; j <= tail; j += 32) {
                int tj = tg[j], tp = tg[j - 1];
                nsum += (double)s_trans[tp * TT + tj] + (double)emb[j * TT + tj];
            }
            #pragma unroll
            for (int o = 16; o; o >>= 1) nsum += __shfl_xor_sync(FULLM, nsum, o);
            int th = tg[head], tl = tg[tail];
            double num = nsum + (double)s_start[th] + (double)emb[head * TT + th] + (double)s_end[tl];

            // ---- E (fwd columns) and E^T (bwd) splits, packed f32x2 ----
            unsigned long long EF_a[8], EF_b[8], EB_a[8], EB_b[8];
            #pragma unroll
            for (int i = 0; i < 8; i++) {
                int t = qbase + i;
                EF_a[i] = pk2(expf(s_trans[t * TT + lane]),
                              expf(s_trans[t * TT + (lane ^ 8)]));
                EF_b[i] = pk2(expf(s_trans[t * TT + (lane ^ 16)]),
                              expf(s_trans[t * TT + (lane ^ 24)]));
                EB_a[i] = pk2(expf(s_trans[lane * TT + t]),
                              expf(s_trans[(lane ^ 8) * TT + t]));
                EB_b[i] = pk2(expf(s_trans[(lane ^ 16) * TT + t]),
                              expf(s_trans[(lane ^ 24) * TT + t]));
            }
            float eend = expf(s_end[lane]);

            // ---- forward init at head ----
            float s2  = (s_start[lane] + emb[head * TT + lane]) * L2E;
            float c20 = __shfl_sync(FULLM, s2, 0);
            float pF  = exp2f(s2 - c20);
            float scF = 1.0f, EMsF = 0.0f;
            int   KaccF = 0, pendF = 0;

            // ---- backward init at tail ----
            float pB = 0.0f, scB = 1.0f, EMsB = 0.0f;
            int   KaccB = 0, pendB = 0;
            if (hasB) {
                float em2t = emb[tail * TT + lane] * L2E;
                float t0i  = __shfl_sync(FULLM, em2t, 0);
                pB   = exp2f(em2t - t0i) * eend;
                EMsB = t0i;
                float v0n = __shfl_sync(FULLM, pB, 0);
                int   e0  = __float_as_int(v0n) >> 23;
                pendB = e0 - 127;
                scB   = __int_as_float((254 - e0) << 23);
            }

            const int nF = mid - head;
            const int nB = hasB ? (tail - mid - 1) : 0;
            const int nmin = (nF < nB) ? nF : nB;

            // emission index helpers (clamped; over-reads harmless)
            #define JF(s_) min(head + 1 + (s_), SLEN - 1)
            #define JB(s_) max(tail - 1 - (s_), 0)

            // ---- paired mainloop, groups of 2 steps, 1-group lookahead ----
            int s = 0;
            float rF2 = emb[JF(2) * TT + lane], rF3 = emb[JF(3) * TT + lane];
            float rB2 = emb[JB(2) * TT + lane], rB3 = emb[JB(3) * TT + lane];
            float eF0, eF1, mF0, mF1, eB0, eB1, mB0, mB1;
            {
                float tF0 = emb[JF(0) * TT + lane] * L2E;
                float tF1 = emb[JF(1) * TT + lane] * L2E;
                float tB0 = emb[JB(0) * TT + lane] * L2E;
                float tB1 = emb[JB(1) * TT + lane] * L2E;
                float z;
                z = __shfl_sync(FULLM, tF0, 0); eF0 = ex2f_(tF0 - z); mF0 = z;
                z = __shfl_sync(FULLM, tF1, 0); eF1 = ex2f_(tF1 - z); mF1 = z;
                z = __shfl_sync(FULLM, tB0, 0); eB0 = ex2f_(tB0 - z); mB0 = z;
                z = __shfl_sync(FULLM, tB1, 0); eB1 = ex2f_(tB1 - z); mB1 = z;
            }

            while (s + 2 <= nmin) {
                // prefetch raw for group s+4
                float nF0 = emb[JF(s + 4) * TT + lane];
                float nF1 = emb[JF(s + 5) * TT + lane];
                float nB0 = emb[JB(s + 4) * TT + lane];
                float nB1 = emb[JB(s + 5) * TT + lane];
                // convert group s+2
                float eF2, eF3, mF2, mF3, eB2, eB3, mB2, mB3;
                {
                    float t0 = rF2 * L2E, t1 = rF3 * L2E;
                    float t2 = rB2 * L2E, t3 = rB3 * L2E;
                    float z;
                    z = __shfl_sync(FULLM, t0, 0); eF2 = ex2f_(t0 - z); mF2 = z;
                    z = __shfl_sync(FULLM, t1, 0); eF3 = ex2f_(t1 - z); mF3 = z;
                    z = __shfl_sync(FULLM, t2, 0); eB2 = ex2f_(t2 - z); mB2 = z;
                    z = __shfl_sync(FULLM, t3, 0); eB3 = ex2f_(t3 - z); mB3 = z;
                }

                // step 0 (applies pending scale)
                float aF = dotq(pF, qbase, EF_a, EF_b);
                float aB = dotq(pB, qbase, EB_a, EB_b);
                pF = aF * (eF0 * scF);
                pB = aB * (eB0 * scB);
                EMsF += mF0; EMsB += mB0;

                // step 1 (no scale), then extract new scale
                aF = dotq(pF, qbase, EF_a, EF_b);
                aB = dotq(pB, qbase, EB_a, EB_b);
                pF = aF * eF1;
                pB = aB * eB1;
                EMsF += mF1; EMsB += mB1;
                extract_scale(pF, KaccF, pendF, scF);
                extract_scale(pB, KaccB, pendB, scB);

                eF0 = eF2; eF1 = eF3; mF0 = mF2; mF1 = mF3;
                eB0 = eB2; eB1 = eB3; mB0 = mB2; mB1 = mB3;
                rF2 = nF0; rF3 = nF1; rB2 = nB0; rB3 = nB1;
                s += 2;
            }

            // ---- generic tails (at most ~2 steps each) ----
            for (int t = s; t < nF; t++) {
                float tr_ = emb[JF(t) * TT + lane] * L2E;
                float z = __shfl_sync(FULLM, tr_, 0);
                float e = ex2f_(tr_ - z);
                float a = dotq(pF, qbase, EF_a, EF_b);
                pF = a * (e * scF);
                EMsF += z;
                extract_scale(pF, KaccF, pendF, scF);
            }
            for (int t = s; t < nB; t++) {
                float tr_ = emb[JB(t) * TT + lane] * L2E;
                float z = __shfl_sync(FULLM, tr_, 0);
                float e = ex2f_(tr_ - z);
                float a = dotq(pB, qbase, EB_a, EB_b);
                pB = a * (e * scB);
                EMsB += z;
                extract_scale(pB, KaccB, pendB, scB);
            }
            // forward: drop last pendF (its sc never applied)

            // ---- backward final dot (no emission), consumes pending scB ----
            float bm;
            if (hasB) {
                float aB = dotq(pB, qbase, EB_a, EB_b);
                bm = aB * scB;
                KaccB += pendB;
            } else {
                bm = eend;
                KaccB = 0; EMsB = 0.0f;
            }

            // ---- combine: Z = sum_t alpha_mid[t] * bm[t] ----
            float vv = pF * bm;
            #pragma unroll
            for (int o = 16; o; o >>= 1) vv += __shfl_xor_sync(FULLM, vv, o);
            const double LN2 = 0.6931471805599453;
            double denom = ((double)c20 + (double)EMsF + (double)KaccF
                            + (double)EMsB + (double)KaccB + (double)log2f(vv)) * LN2;

            if (lane == 0) {
                g_contrib[b] = (denom - num) / ((double)len + 1e-6);
                g_cnt[b]     = 1.0;
            }
            #undef JF
            #undef JB
        } else if (lane == 0) {
            g_contrib[b] = 0.0; g_cnt[b] = 0.0;
        }
    }

    // ---- last-block-done fused reduction (deterministic fixed order) ----
    __syncthreads();
    if (tid == 0) {
        __threadfence();
        s_last = (atomicAdd(&g_sem, 1u) == (unsigned)(gridDim.x - 1));
    }
    __syncthreads();
    if (s_last) {
        __threadfence();
        double a = 0.0, c = 0.0;
        for (int i = tid; i < BATCH; i += THREADS) { a += g_contrib[i]; c += g_cnt[i]; }
        #pragma unroll
        for (int o = 16; o; o >>= 1) {
            a += __shfl_xor_sync(FULLM, a, o);
            c += __shfl_xor_sync(FULLM, c, o);
        }
        if (lane == 0) { s_r1[w] = a; s_r2[w] = c; }
        __syncthreads();
        if (tid == 0) {
            double A = 0.0, C = 0.0;
            for (int i = 0; i < BPB; i++) { A += s_r1[i]; C += s_r2[i]; }
            out[0] = (float)(A / (C + 1e-6));
            g_sem = 0;   // re-arm for next graph replay
        }
    }
}

extern "C" void kernel_launch(void* const* d_in, const int* in_sizes, int n_in,
                              void* d_out, int out_size)
{
    const float* em    = (const float*)d_in[0];
    const int*   tags  = (const int*)d_in[1];
    const void*  mask  = (const void*)d_in[2];
    const float* st    = (const float*)d_in[3];
    const float* tr    = (const float*)d_in[4];
    const float* en    = (const float*)d_in[5];

    crf_fused_kernel<<<NBLK, THREADS>>>(em, tags, mask, st, tr, en, (float*)d_out);
}

// round 13
// speedup vs baseline: 1.1112x; 1.1112x over previous
#include <cuda_runtime.h>

// CRF mean log-likelihood, B=1024, S=1024, T=32.
// Inputs (metadata order): emissions f32 [B,S,T], tags i32 [B,S], mask [B,S]
// (dtype probed at runtime), start f32 [T], transitions f32 [T,T], end f32 [T].
// Output: 1 float.
//
// Per batch: forward warp (head->mid, E) + backward warp (tail->mid, E^T).
// Register-resident scaled recursion; quarter-split matvec (8 shfl gather,
// t-pair packed f32x2 FMAs, 3-shfl reduce). NO per-step emission
// normalization: raw ex2(em) multiplies p; all log-mass tracked by exact
// power-of-2 extraction (pend/Kacc) every 2 steps + one final log2f.

#define BATCH   1024
#define SLEN    1024
#define TT      32
#define BPB     7
#define NWARP   (BPB * 2)
#define THREADS (NWARP * 32)              // 448
#define NBLK    ((BATCH + BPB - 1) / BPB)  // 147 -> one wave
#define FULLM   0xffffffffu

__device__ double   g_contrib[BATCH];
__device__ double   g_cnt[BATCH];
__device__ unsigned g_sem = 0;

__device__ __forceinline__ float ex2f_(float x) { float r; asm("ex2.approx.f32 %0, %1;" : "=f"(r) : "f"(x)); return r; }
__device__ __forceinline__ unsigned long long pk2(float lo, float hi) {
    unsigned long long r; asm("mov.b64 %0, {%1, %2};" : "=l"(r) : "f"(lo), "f"(hi)); return r;
}
__device__ __forceinline__ void fma2(unsigned long long& d, unsigned long long a, unsigned long long b) {
    asm("fma.rn.f32x2 %0, %1, %2, %0;" : "+l"(d) : "l"(a), "l"(b));
}
__device__ __forceinline__ void upk(unsigned long long v, float& x, float& y) {
    asm("mov.b64 {%0, %1}, %2;" : "=f"(x), "=f"(y) : "l"(v));
}

// Probe mask dtype from its first bytes (mask[0]=mask[1]=true since len>=256).
__device__ __forceinline__ int probe_mask_mode(const void* m) {
    const unsigned char* u = (const unsigned char*)m;
    if (u[0] != 0 && u[1] != 0) return 0;           // u8 / bool
    if (u[0] == 0) return (u[3] != 0) ? 2 : 4;      // f32 : f64
    return (u[4] != 0) ? 1 : 3;                     // i32 : i64
}
__device__ __forceinline__ bool mask_at(const void* m, int mode, size_t k) {
    switch (mode) {
        case 0:  return ((const unsigned char*)m)[k] != 0;
        case 1:  return ((const int*)m)[k] != 0;
        case 2:  return ((const float*)m)[k] != 0.0f;
        default: { const int* p = (const int*)m; return (p[2*k] | p[2*k+1]) != 0; } // 64-bit
    }
}

// Quarter-split matvec, t-pair packed. E holds 16 packed pairs:
// E[4*j + i] = ( e[t0][c_j], e[t0+1][c_j] ), t0 = 8*q + 2*i,
// c_0..3 = lane, lane^8, lane^16, lane^24.
__device__ __forceinline__ float dotq2(float pcur, int qbase,
                                       const unsigned long long* __restrict__ E)
{
    float bb[8];
    #pragma unroll
    for (int i = 0; i < 8; i++) bb[i] = __shfl_sync(FULLM, pcur, qbase + i);

    unsigned long long bp[4];
    #pragma unroll
    for (int i = 0; i < 4; i++) bp[i] = pk2(bb[2 * i], bb[2 * i + 1]);

    unsigned long long A0 = 0ull, A1 = 0ull, A2 = 0ull, A3 = 0ull;
    #pragma unroll
    for (int i = 0; i < 4; i++) {
        fma2(A0, bp[i], E[i]);
        fma2(A1, bp[i], E[4 + i]);
        fma2(A2, bp[i], E[8 + i]);
        fma2(A3, bp[i], E[12 + i]);
    }
    float x0, y0, x1, y1, x2, y2, x3, y3;
    upk(A0, x0, y0); upk(A1, x1, y1); upk(A2, x2, y2); upk(A3, x3, y3);
    float r0 = x0 + y0, r1 = x1 + y1, r2 = x2 + y2, r3 = x3 + y3;

    float a0 = r0 + __shfl_xor_sync(FULLM, r1, 8);
    float a2 = r2 + __shfl_xor_sync(FULLM, r3, 8);
    return a0 + __shfl_xor_sync(FULLM, a2, 16);
}

__device__ __forceinline__ void extract_scale(float p, int& Kacc, int& pend, float& sc)
{
    float p0 = __shfl_sync(FULLM, p, 0);
    int e = __float_as_int(p0) >> 23;
    Kacc += pend; pend = e - 127;
    sc = __int_as_float((254 - e) << 23);
}

// n steps of the scaled recursion. Each step: p' = (matvec p) * ex2(em*L2E),
// with the pending power-of-2 scale applied on even steps, extraction after
// every 2 steps (and after a trailing odd step).
template<int DIR>
__device__ __forceinline__ void run_chain(
    const float* __restrict__ emb, int jstart, int n, int lane, int qbase,
    const unsigned long long* __restrict__ E,
    float& pcur, float& sc, int& Kacc, int& pend)
{
    if (n <= 0) return;
    const float L2E = 1.4426950408889634f;

    #define JIDX(s_) ((DIR > 0) ? min(jstart + (s_), SLEN - 1) : max(jstart - (s_), 0))

    float e0  = ex2f_(emb[JIDX(0) * TT + lane] * L2E);
    float e1  = ex2f_(emb[JIDX(1) * TT + lane] * L2E);
    float rA0 = emb[JIDX(2) * TT + lane], rA1 = emb[JIDX(3) * TT + lane];
    float rB0 = emb[JIDX(4) * TT + lane], rB1 = emb[JIDX(5) * TT + lane];
    float esc = e0 * sc;

    int s = 0;
    while (s + 2 <= n) {
        float rC0 = emb[JIDX(s + 6) * TT + lane];
        float rC1 = emb[JIDX(s + 7) * TT + lane];

        pcur = dotq2(pcur, qbase, E) * esc;   // even step: applies pending scale
        pcur = dotq2(pcur, qbase, E) * e1;    // odd step
        extract_scale(pcur, Kacc, pend, sc);

        e0  = ex2f_(rA0 * L2E);
        e1  = ex2f_(rA1 * L2E);
        esc = e0 * sc;
        rA0 = rB0; rA1 = rB1; rB0 = rC0; rB1 = rC1;
        s += 2;
    }
    if (s < n) {                              // trailing odd step
        pcur = dotq2(pcur, qbase, E) * esc;
        extract_scale(pcur, Kacc, pend, sc);
    }
    #undef JIDX
}

__global__ void __launch_bounds__(THREADS)
crf_fused_kernel(const float* __restrict__ em,
                 const int* __restrict__ tags,
                 const void* __restrict__ maskp,
                 const float* __restrict__ startv,
                 const float* __restrict__ transv,
                 const float* __restrict__ endv,
                 float* __restrict__ out)
{
    __shared__ float s_trans[TT * TT];
    __shared__ float s_start[TT];
    __shared__ float s_end[TT];
    __shared__ __align__(16) float s_bm[BPB][TT];   // B_mid from backward warp
    __shared__ double s_nb[BPB];                    // backward numerator partial
    __shared__ int    s_kb[BPB];                    // backward Kacc
    __shared__ double s_r1[NWARP], s_r2[NWARP];
    __shared__ bool   s_last;

    const int  tid   = threadIdx.x;
    const int  w     = tid >> 5;
    const int  lane  = tid & 31;
    const bool isF   = (w < BPB);
    const int  slot  = isF ? w : (w - BPB);
    const int  b     = blockIdx.x * BPB + slot;
    const int  qbase = (lane >> 3) << 3;

    for (int i = tid; i < TT * TT; i += THREADS) s_trans[i] = transv[i];
    if (tid < TT) { s_start[tid] = startv[tid]; s_end[tid] = endv[tid]; }
    __syncthreads();

    const float L2E = 1.4426950408889634f;

    int head = 0, tail = -1, len = 0;
    if (b < BATCH) {
        const int mmode = probe_mask_mode(maskp);
        const size_t mbase = (size_t)b * SLEN;
        int h = -1;
        #pragma unroll 4
        for (int i = 0; i < SLEN / 32; i++) {
            bool mv = mask_at(maskp, mmode, mbase + i * 32 + lane);
            unsigned bits = __ballot_sync(FULLM, mv);
            len += __popc(bits);
            if (bits) {
                if (h < 0) h = i * 32 + (__ffs(bits) - 1);
                tail = i * 32 + 31 - __clz(bits);
            }
        }
        head = (h < 0) ? 0 : h;
    }

    const bool active = (b < BATCH) && (len > 0);
    float  pF = 0.0f;
    int    KaccF = 0;
    double nsumF = 0.0;

    if (active) {
        const float* emb = em + (size_t)b * SLEN * TT;
        const int*   tg  = tags + (size_t)b * SLEN;
        const int    mid  = (head + tail) >> 1;
        const bool   hasB = (tail > mid);

        if (isF) {
            // ---------- FORWARD WARP ----------
            double nsum = 0.0;
            #pragma unroll 4
            for (int j = head + 1 + lane; j <= mid; j += 32) {
                int tj = tg[j], tp = tg[j - 1];
                nsum += (double)s_trans[tp * TT + tj] + (double)emb[j * TT + tj];
            }
            #pragma unroll
            for (int o = 16; o; o >>= 1) nsum += __shfl_xor_sync(FULLM, nsum, o);
            int th = tg[head], tl = tg[tail];
            nsumF = nsum + (double)s_start[th] + (double)emb[head * TT + th] + (double)s_end[tl];

            // E (fwd): E[4j+i] = (e^trans[t0][c_j], e^trans[t0+1][c_j])
            unsigned long long E[16];
            #pragma unroll
            for (int jj = 0; jj < 4; jj++) {
                int c = lane ^ (jj << 3);
                #pragma unroll
                for (int i = 0; i < 4; i++) {
                    int t0 = qbase + 2 * i;
                    E[4 * jj + i] = pk2(expf(s_trans[t0 * TT + c]),
                                        expf(s_trans[(t0 + 1) * TT + c]));
                }
            }

            // init at head: raw exp2 of (start+em), no normalization
            pF = exp2f((s_start[lane] + emb[head * TT + lane]) * L2E);
            float sc = 1.0f; int pend = 0;
            run_chain<1>(emb, head + 1, mid - head, lane, qbase, E, pF, sc, KaccF, pend);
            // drop final pend (its sc never applied)
        } else {
            // ---------- BACKWARD WARP ----------
            double nsum = 0.0;
            #pragma unroll 4
            for (int j = mid + 1 + lane; j <= tail; j += 32) {
                int tj = tg[j], tp = tg[j - 1];
                nsum += (double)s_trans[tp * TT + tj] + (double)emb[j * TT + tj];
            }
            #pragma unroll
            for (int o = 16; o; o >>= 1) nsum += __shfl_xor_sync(FULLM, nsum, o);
            if (lane == 0) s_nb[slot] = nsum;

            // E^T (bwd): E[4j+i] = (e^trans[c_j][t0], e^trans[c_j][t0+1])
            unsigned long long E[16];
            #pragma unroll
            for (int jj = 0; jj < 4; jj++) {
                int c = lane ^ (jj << 3);
                #pragma unroll
                for (int i = 0; i < 4; i++) {
                    int t0 = qbase + 2 * i;
                    E[4 * jj + i] = pk2(expf(s_trans[c * TT + t0]),
                                        expf(s_trans[c * TT + t0 + 1]));
                }
            }

            float bm;
            int   KaccB = 0;
            if (hasB) {
                float pB = ex2f_(emb[tail * TT + lane] * L2E) * expf(s_end[lane]);
                int pend;
                float sc;
                {   // initial extraction
                    float p0 = __shfl_sync(FULLM, pB, 0);
                    int e = __float_as_int(p0) >> 23;
                    pend = e - 127;
                    sc = __int_as_float((254 - e) << 23);
                }
                run_chain<-1>(emb, tail - 1, tail - mid - 1, lane, qbase, E, pB, sc, KaccB, pend);
                // final dot (no emission): consumes pending sc
                bm = dotq2(pB, qbase, E) * sc;
                KaccB += pend;
            } else {
                bm = expf(s_end[lane]);
            }
            s_bm[slot][lane] = bm;
            if (lane == 0) s_kb[slot] = KaccB;
        }
    } else if (b < BATCH && isF && lane == 0) {
        g_contrib[b] = 0.0; g_cnt[b] = 0.0;
    }

    __syncthreads();   // backward results (s_bm, s_nb, s_kb) visible

    if (active && isF) {
        float vv = pF * s_bm[slot][lane];
        #pragma unroll
        for (int o = 16; o; o >>= 1) vv += __shfl_xor_sync(FULLM, vv, o);
        const double LN2 = 0.6931471805599453;
        double denom = ((double)KaccF + (double)s_kb[slot] + (double)log2f(vv)) * LN2;
        double num   = nsumF + s_nb[slot];
        if (lane == 0) {
            g_contrib[b] = (denom - num) / ((double)len + 1e-6);
            g_cnt[b]     = 1.0;
        }
    }

    // ---- last-block-done fused reduction (deterministic fixed order) ----
    __syncthreads();
    if (tid == 0) {
        __threadfence();
        s_last = (atomicAdd(&g_sem, 1u) == (unsigned)(gridDim.x - 1));
    }
    __syncthreads();
    if (s_last) {
        __threadfence();
        double a = 0.0, c = 0.0;
        for (int i = tid; i < BATCH; i += THREADS) { a += g_contrib[i]; c += g_cnt[i]; }
        #pragma unroll
        for (int o = 16; o; o >>= 1) {
            a += __shfl_xor_sync(FULLM, a, o);
            c += __shfl_xor_sync(FULLM, c, o);
        }
        if (lane == 0) { s_r1[w] = a; s_r2[w] = c; }
        __syncthreads();
        if (tid == 0) {
            double A = 0.0, C = 0.0;
            for (int i = 0; i < NWARP; i++) { A += s_r1[i]; C += s_r2[i]; }
            out[0] = (float)(A / (C + 1e-6));
            g_sem = 0;   // re-arm for next graph replay
        }
    }
}

extern "C" void kernel_launch(void* const* d_in, const int* in_sizes, int n_in,
                              void* d_out, int out_size)
{
    const float* em    = (const float*)d_in[0];
    const int*   tags  = (const int*)d_in[1];
    const void*  mask  = (const void*)d_in[2];
    const float* st    = (const float*)d_in[3];
    const float* tr    = (const float*)d_in[4];
    const float* en    = (const float*)d_in[5];

    crf_fused_kernel<<<NBLK, THREADS>>>(em, tags, mask, st, tr, en, (float*)d_out);
}

// round 14
// speedup vs baseline: 1.2213x; 1.0991x over previous
#include <cuda_runtime.h>

// CRF mean log-likelihood, B=1024, S=1024, T=32.
// Inputs (metadata order): emissions f32 [B,S,T], tags i32 [B,S], mask [B,S]
// (dtype probed at runtime), start f32 [T], transitions f32 [T,T], end f32 [T].
// Output: 1 float.
//
// Per batch: forward warp (head->mid, E) + backward warp (tail->mid, E^T).
// Register-resident scaled recursion; quarter-split matvec: 8-shfl gather,
// t-pair packed f32x2 FMAs (4 accums x depth 4), 3 INDEPENDENT shfl_xor
// reduce. No per-step emission normalization: raw ex2(em) multiplies p; all
// log-mass tracked by exact power-of-2 extraction (pend/Kacc) every 2 steps
// + one final log2f. Group-of-4 software pipeline on emissions.

#define BATCH   1024
#define SLEN    1024
#define TT      32
#define BPB     7
#define NWARP   (BPB * 2)
#define THREADS (NWARP * 32)               // 448
#define NBLK    ((BATCH + BPB - 1) / BPB)  // 147 -> one wave
#define FULLM   0xffffffffu

__device__ double   g_contrib[BATCH];
__device__ double   g_cnt[BATCH];
__device__ unsigned g_sem = 0;

__device__ __forceinline__ float ex2f_(float x) { float r; asm("ex2.approx.f32 %0, %1;" : "=f"(r) : "f"(x)); return r; }
__device__ __forceinline__ unsigned long long pk2(float lo, float hi) {
    unsigned long long r; asm("mov.b64 %0, {%1, %2};" : "=l"(r) : "f"(lo), "f"(hi)); return r;
}
__device__ __forceinline__ void fma2(unsigned long long& d, unsigned long long a, unsigned long long b) {
    asm("fma.rn.f32x2 %0, %1, %2, %0;" : "+l"(d) : "l"(a), "l"(b));
}
__device__ __forceinline__ void upk(unsigned long long v, float& x, float& y) {
    asm("mov.b64 {%0, %1}, %2;" : "=f"(x), "=f"(y) : "l"(v));
}

// Probe mask dtype from its first bytes (mask[0]=mask[1]=true since len>=256).
__device__ __forceinline__ int probe_mask_mode(const void* m) {
    const unsigned char* u = (const unsigned char*)m;
    if (u[0] != 0 && u[1] != 0) return 0;           // u8 / bool
    if (u[0] == 0) return (u[3] != 0) ? 2 : 4;      // f32 : f64
    return (u[4] != 0) ? 1 : 3;                     // i32 : i64
}
__device__ __forceinline__ bool mask_at(const void* m, int mode, size_t k) {
    switch (mode) {
        case 0:  return ((const unsigned char*)m)[k] != 0;
        case 1:  return ((const int*)m)[k] != 0;
        case 2:  return ((const float*)m)[k] != 0.0f;
        default: { const int* p = (const int*)m; return (p[2*k] | p[2*k+1]) != 0; } // 64-bit
    }
}

// Quarter-split matvec, t-pair packed. E holds 16 packed pairs:
// E[4*j + i] = ( e[t0][c_j], e[t0+1][c_j] ), t0 = qbase + 2*i,
// c_0..3 = lane, lane^8, lane^16, lane^24.
// Reduce uses 3 INDEPENDENT shfl_xor (one MIO stage).
__device__ __forceinline__ float dotq(float pcur, int qbase,
                                      const unsigned long long* __restrict__ E)
{
    float bb[8];
    #pragma unroll
    for (int i = 0; i < 8; i++) bb[i] = __shfl_sync(FULLM, pcur, qbase + i);

    unsigned long long bp[4];
    #pragma unroll
    for (int i = 0; i < 4; i++) bp[i] = pk2(bb[2 * i], bb[2 * i + 1]);

    unsigned long long A0 = 0ull, A1 = 0ull, A2 = 0ull, A3 = 0ull;
    #pragma unroll
    for (int i = 0; i < 4; i++) {
        fma2(A0, bp[i], E[i]);
        fma2(A1, bp[i], E[4 + i]);
        fma2(A2, bp[i], E[8 + i]);
        fma2(A3, bp[i], E[12 + i]);
    }
    float x0, y0, x1, y1, x2, y2, x3, y3;
    upk(A0, x0, y0); upk(A1, x1, y1); upk(A2, x2, y2); upk(A3, x3, y3);
    float r0 = x0 + y0, r1 = x1 + y1, r2 = x2 + y2, r3 = x3 + y3;

    float s1 = __shfl_xor_sync(FULLM, r1, 8);    // independent
    float s2 = __shfl_xor_sync(FULLM, r2, 16);   // independent
    float s3 = __shfl_xor_sync(FULLM, r3, 24);   // independent
    return (r0 + s1) + (s2 + s3);
}

__device__ __forceinline__ void extract_scale(float p, int& Kacc, int& pend, float& sc)
{
    float p0 = __shfl_sync(FULLM, p, 0);
    int e = __float_as_int(p0) >> 23;
    Kacc += pend; pend = e - 127;
    sc = __int_as_float((254 - e) << 23);
}

// n steps: p' = (matvec p) * ex2(em*L2E); pending power-of-2 scale applied on
// even steps, extraction after odd steps. Group-of-4 emission pipeline.
template<int DIR>
__device__ __forceinline__ void run_chain(
    const float* __restrict__ emb, int jstart, int n, int lane, int qbase,
    const unsigned long long* __restrict__ E,
    float& pcur, float& sc, int& Kacc, int& pend)
{
    if (n <= 0) return;
    const float L2E = 1.4426950408889634f;

    #define JIDX(s_) ((DIR > 0) ? min(jstart + (s_), SLEN - 1) : max(jstart - (s_), 0))

    float e[4], raw[4];
    #pragma unroll
    for (int i = 0; i < 4; i++) e[i]   = ex2f_(emb[JIDX(i) * TT + lane] * L2E);
    #pragma unroll
    for (int i = 0; i < 4; i++) raw[i] = emb[JIDX(4 + i) * TT + lane];

    int s = 0;
    while (s + 4 <= n) {
        float nraw[4], en[4];
        #pragma unroll
        for (int i = 0; i < 4; i++) nraw[i] = emb[JIDX(s + 8 + i) * TT + lane];
        #pragma unroll
        for (int i = 0; i < 4; i++) en[i] = ex2f_(raw[i] * L2E);

        pcur = dotq(pcur, qbase, E) * (e[0] * sc);   // even: applies pending scale
        pcur = dotq(pcur, qbase, E) * e[1];
        extract_scale(pcur, Kacc, pend, sc);
        pcur = dotq(pcur, qbase, E) * (e[2] * sc);
        pcur = dotq(pcur, qbase, E) * e[3];
        extract_scale(pcur, Kacc, pend, sc);

        #pragma unroll
        for (int i = 0; i < 4; i++) { e[i] = en[i]; raw[i] = nraw[i]; }
        s += 4;
    }
    #pragma unroll
    for (int k = 0; k < 4; k++) {
        if (s < n) {
            pcur = dotq(pcur, qbase, E) * (e[k] * sc);
            extract_scale(pcur, Kacc, pend, sc);
            s++;
        }
    }
    #undef JIDX
}

__global__ void __launch_bounds__(THREADS)
crf_fused_kernel(const float* __restrict__ em,
                 const int* __restrict__ tags,
                 const void* __restrict__ maskp,
                 const float* __restrict__ startv,
                 const float* __restrict__ transv,
                 const float* __restrict__ endv,
                 float* __restrict__ out)
{
    __shared__ float s_trans[TT * TT];
    __shared__ float s_start[TT];
    __shared__ float s_end[TT];
    __shared__ __align__(16) float s_bm[BPB][TT];   // B_mid from backward warp
    __shared__ double s_nb[BPB];                    // backward numerator partial
    __shared__ int    s_kb[BPB];                    // backward Kacc
    __shared__ double s_r1[NWARP], s_r2[NWARP];
    __shared__ bool   s_last;

    const int  tid   = threadIdx.x;
    const int  w     = tid >> 5;
    const int  lane  = tid & 31;
    const bool isF   = (w < BPB);
    const int  slot  = isF ? w : (w - BPB);
    const int  b     = blockIdx.x * BPB + slot;
    const int  qbase = (lane >> 3) << 3;

    for (int i = tid; i < TT * TT; i += THREADS) s_trans[i] = transv[i];
    if (tid < TT) { s_start[tid] = startv[tid]; s_end[tid] = endv[tid]; }
    __syncthreads();

    const float L2E = 1.4426950408889634f;

    int head = 0, tail = -1, len = 0;
    if (b < BATCH) {
        const int mmode = probe_mask_mode(maskp);
        const size_t mbase = (size_t)b * SLEN;
        int h = -1;
        #pragma unroll 4
        for (int i = 0; i < SLEN / 32; i++) {
            bool mv = mask_at(maskp, mmode, mbase + i * 32 + lane);
            unsigned bits = __ballot_sync(FULLM, mv);
            len += __popc(bits);
            if (bits) {
                if (h < 0) h = i * 32 + (__ffs(bits) - 1);
                tail = i * 32 + 31 - __clz(bits);
            }
        }
        head = (h < 0) ? 0 : h;
    }

    const bool active = (b < BATCH) && (len > 0);
    float  pF = 0.0f;
    int    KaccF = 0;
    double nsumF = 0.0;

    if (active) {
        const float* emb = em + (size_t)b * SLEN * TT;
        const int*   tg  = tags + (size_t)b * SLEN;
        const int    mid  = (head + tail) >> 1;
        const bool   hasB = (tail > mid);

        if (isF) {
            // ---------- FORWARD WARP ----------
            double nsum = 0.0;
            #pragma unroll 4
            for (int j = head + 1 + lane; j <= mid; j += 32) {
                int tj = tg[j], tp = tg[j - 1];
                nsum += (double)s_trans[tp * TT + tj] + (double)emb[j * TT + tj];
            }
            #pragma unroll
            for (int o = 16; o; o >>= 1) nsum += __shfl_xor_sync(FULLM, nsum, o);
            int th = tg[head], tl = tg[tail];
            nsumF = nsum + (double)s_start[th] + (double)emb[head * TT + th] + (double)s_end[tl];

            // E (fwd): E[4j+i] = (e^trans[t0][c_j], e^trans[t0+1][c_j])
            unsigned long long E[16];
            #pragma unroll
            for (int jj = 0; jj < 4; jj++) {
                int c = lane ^ (jj << 3);
                #pragma unroll
                for (int i = 0; i < 4; i++) {
                    int t0 = qbase + 2 * i;
                    E[4 * jj + i] = pk2(expf(s_trans[t0 * TT + c]),
                                        expf(s_trans[(t0 + 1) * TT + c]));
                }
            }

            // init at head: raw exp2 of (start+em), no normalization
            pF = exp2f((s_start[lane] + emb[head * TT + lane]) * L2E);
            float sc = 1.0f; int pend = 0;
            run_chain<1>(emb, head + 1, mid - head, lane, qbase, E, pF, sc, KaccF, pend);
            // drop final pend (its sc never applied)
        } else {
            // ---------- BACKWARD WARP ----------
            double nsum = 0.0;
            #pragma unroll 4
            for (int j = mid + 1 + lane; j <= tail; j += 32) {
                int tj = tg[j], tp = tg[j - 1];
                nsum += (double)s_trans[tp * TT + tj] + (double)emb[j * TT + tj];
            }
            #pragma unroll
            for (int o = 16; o; o >>= 1) nsum += __shfl_xor_sync(FULLM, nsum, o);
            if (lane == 0) s_nb[slot] = nsum;

            // E^T (bwd): E[4j+i] = (e^trans[c_j][t0], e^trans[c_j][t0+1])
            unsigned long long E[16];
            #pragma unroll
            for (int jj = 0; jj < 4; jj++) {
                int c = lane ^ (jj << 3);
                #pragma unroll
                for (int i = 0; i < 4; i++) {
                    int t0 = qbase + 2 * i;
                    E[4 * jj + i] = pk2(expf(s_trans[c * TT + t0]),
                                        expf(s_trans[c * TT + t0 + 1]));
                }
            }

            float bm;
            int   KaccB = 0;
            if (hasB) {
                float pB = ex2f_(emb[tail * TT + lane] * L2E) * expf(s_end[lane]);
                int pend;
                float sc;
                {   // initial extraction
                    float p0 = __shfl_sync(FULLM, pB, 0);
                    int e = __float_as_int(p0) >> 23;
                    pend = e - 127;
                    sc = __int_as_float((254 - e) << 23);
                }
                run_chain<-1>(emb, tail - 1, tail - mid - 1, lane, qbase, E, pB, sc, KaccB, pend);
                // final dot (no emission): consumes pending sc
                bm = dotq(pB, qbase, E) * sc;
                KaccB += pend;
            } else {
                bm = expf(s_end[lane]);
            }
            s_bm[slot][lane] = bm;
            if (lane == 0) s_kb[slot] = KaccB;
        }
    } else if (b < BATCH && isF && lane == 0) {
        g_contrib[b] = 0.0; g_cnt[b] = 0.0;
    }

    __syncthreads();   // backward results (s_bm, s_nb, s_kb) visible

    if (active && isF) {
        float vv = pF * s_bm[slot][lane];
        #pragma unroll
        for (int o = 16; o; o >>= 1) vv += __shfl_xor_sync(FULLM, vv, o);
        const double LN2 = 0.6931471805599453;
        double denom = ((double)KaccF + (double)s_kb[slot] + (double)log2f(vv)) * LN2;
        double num   = nsumF + s_nb[slot];
        if (lane == 0) {
            g_contrib[b] = (denom - num) / ((double)len + 1e-6);
            g_cnt[b]     = 1.0;
        }
    }

    // ---- last-block-done fused reduction (deterministic fixed order) ----
    __syncthreads();
    if (tid == 0) {
        __threadfence();
        s_last = (atomicAdd(&g_sem, 1u) == (unsigned)(gridDim.x - 1));
    }
    __syncthreads();
    if (s_last) {
        __threadfence();
        double a = 0.0, c = 0.0;
        for (int i = tid; i < BATCH; i += THREADS) { a += g_contrib[i]; c += g_cnt[i]; }
        #pragma unroll
        for (int o = 16; o; o >>= 1) {
            a += __shfl_xor_sync(FULLM, a, o);
            c += __shfl_xor_sync(FULLM, c, o);
        }
        if (lane == 0) { s_r1[w] = a; s_r2[w] = c; }
        __syncthreads();
        if (tid == 0) {
            double A = 0.0, C = 0.0;
            for (int i = 0; i < NWARP; i++) { A += s_r1[i]; C += s_r2[i]; }
            out[0] = (float)(A / (C + 1e-6));
            g_sem = 0;   // re-arm for next graph replay
        }
    }
}

extern "C" void kernel_launch(void* const* d_in, const int* in_sizes, int n_in,
                              void* d_out, int out_size)
{
    const float* em    = (const float*)d_in[0];
    const int*   tags  = (const int*)d_in[1];
    const void*  mask  = (const void*)d_in[2];
    const float* st    = (const float*)d_in[3];
    const float* tr    = (const float*)d_in[4];
    const float* en    = (const float*)d_in[5];

    crf_fused_kernel<<<NBLK, THREADS>>>(em, tags, mask, st, tr, en, (float*)d_out);
}

// round 15
// speedup vs baseline: 1.2366x; 1.0125x over previous
#include <cuda_runtime.h>

// CRF mean log-likelihood, B=1024, S=1024, T=32.
// Inputs (metadata order): emissions f32 [B,S,T], tags i32 [B,S], mask [B,S]
// (dtype probed at runtime), start f32 [T], transitions f32 [T,T], end f32 [T].
// Output: 1 float.
//
// Per batch: forward warp (head->mid, E) + backward warp (tail->mid, E^T).
// Scaled recursion; per-step exchange via double-buffered smem:
//   STS.32 p'_k -> __syncwarp -> 2x LDS.128 (8-lane broadcast, own quarter)
// replacing the 8-shfl gather (4B/op) with 16B/op LDS. FMA: t-pair packed
// f32x2, 4 accums; reduce: 3 independent shfl_xor. No per-step emission
// normalization; exact power-of-2 extraction (pend/Kacc) every 2 steps,
// one final log2f.

#define BATCH   1024
#define SLEN    1024
#define TT      32
#define BPB     7
#define NWARP   (BPB * 2)
#define THREADS (NWARP * 32)               // 448
#define NBLK    ((BATCH + BPB - 1) / BPB)  // 147 -> one wave
#define FULLM   0xffffffffu

__device__ double   g_contrib[BATCH];
__device__ double   g_cnt[BATCH];
__device__ unsigned g_sem = 0;

__device__ __forceinline__ float ex2f_(float x) { float r; asm("ex2.approx.f32 %0, %1;" : "=f"(r) : "f"(x)); return r; }
__device__ __forceinline__ unsigned long long pk2(float lo, float hi) {
    unsigned long long r; asm("mov.b64 %0, {%1, %2};" : "=l"(r) : "f"(lo), "f"(hi)); return r;
}
__device__ __forceinline__ void fma2(unsigned long long& d, unsigned long long a, unsigned long long b) {
    asm("fma.rn.f32x2 %0, %1, %2, %0;" : "+l"(d) : "l"(a), "l"(b));
}
__device__ __forceinline__ void upk(unsigned long long v, float& x, float& y) {
    asm("mov.b64 {%0, %1}, %2;" : "=f"(x), "=f"(y) : "l"(v));
}

// Probe mask dtype from its first bytes (mask[0]=mask[1]=true since len>=256).
__device__ __forceinline__ int probe_mask_mode(const void* m) {
    const unsigned char* u = (const unsigned char*)m;
    if (u[0] != 0 && u[1] != 0) return 0;           // u8 / bool
    if (u[0] == 0) return (u[3] != 0) ? 2 : 4;      // f32 : f64
    return (u[4] != 0) ? 1 : 3;                     // i32 : i64
}
__device__ __forceinline__ bool mask_at(const void* m, int mode, size_t k) {
    switch (mode) {
        case 0:  return ((const unsigned char*)m)[k] != 0;
        case 1:  return ((const int*)m)[k] != 0;
        case 2:  return ((const float*)m)[k] != 0.0f;
        default: { const int* p = (const int*)m; return (p[2*k] | p[2*k+1]) != 0; } // 64-bit
    }
}

// Matvec from smem buffer holding current p (32 floats).
// Lane k reads its quarter (qbase..qbase+7, broadcast within 8-lane group),
// computes partials for cols k, k^8, k^16, k^24, reduces with 3 independent
// shfl_xor. E layout: E[4*j + i] = (e[t0][c_j], e[t0+1][c_j]), t0=qbase+2i,
// c_j = lane ^ (j<<3).
__device__ __forceinline__ float dot_smem(const float* __restrict__ buf, int qbase,
                                          const unsigned long long* __restrict__ E)
{
    __syncwarp();   // make previous STS visible warp-wide
    float4 lo = *(const float4*)(buf + qbase);
    float4 hi = *(const float4*)(buf + qbase + 4);
    unsigned long long bp[4];
    bp[0] = pk2(lo.x, lo.y); bp[1] = pk2(lo.z, lo.w);
    bp[2] = pk2(hi.x, hi.y); bp[3] = pk2(hi.z, hi.w);

    unsigned long long A0 = 0ull, A1 = 0ull, A2 = 0ull, A3 = 0ull;
    #pragma unroll
    for (int i = 0; i < 4; i++) {
        fma2(A0, bp[i], E[i]);
        fma2(A1, bp[i], E[4 + i]);
        fma2(A2, bp[i], E[8 + i]);
        fma2(A3, bp[i], E[12 + i]);
    }
    float x0, y0, x1, y1, x2, y2, x3, y3;
    upk(A0, x0, y0); upk(A1, x1, y1); upk(A2, x2, y2); upk(A3, x3, y3);
    float r0 = x0 + y0, r1 = x1 + y1, r2 = x2 + y2, r3 = x3 + y3;

    float s1 = __shfl_xor_sync(FULLM, r1, 8);    // independent
    float s2 = __shfl_xor_sync(FULLM, r2, 16);   // independent
    float s3 = __shfl_xor_sync(FULLM, r3, 24);   // independent
    return (r0 + s1) + (s2 + s3);
}

__device__ __forceinline__ void extract_scale(float p, int& Kacc, int& pend, float& sc)
{
    float p0 = __shfl_sync(FULLM, p, 0);
    int e = __float_as_int(p0) >> 23;
    Kacc += pend; pend = e - 127;
    sc = __int_as_float((254 - e) << 23);
}

// n steps: p' = (matvec p) * ex2(em*L2E); pending power-of-2 scale applied on
// even steps, extraction after odd steps. Group-of-4 emission pipeline.
// bufs = this warp's double buffer (2 x 32 floats); par = buffer holding p.
template<int DIR>
__device__ __forceinline__ void run_chain(
    const float* __restrict__ emb, int jstart, int n, int lane, int qbase,
    const unsigned long long* __restrict__ E,
    float (*bufs)[TT], int& par,
    float& pcur, float& sc, int& Kacc, int& pend)
{
    if (n <= 0) return;
    const float L2E = 1.4426950408889634f;

    #define JIDX(s_) ((DIR > 0) ? min(jstart + (s_), SLEN - 1) : max(jstart - (s_), 0))
    #define STEP(emul)                                            \
        do {                                                      \
            float acc_ = dot_smem(bufs[par], qbase, E);           \
            pcur = acc_ * (emul);                                 \
            bufs[par ^ 1][lane] = pcur;                           \
            par ^= 1;                                             \
        } while (0)

    float e[4], raw[4];
    #pragma unroll
    for (int i = 0; i < 4; i++) e[i]   = ex2f_(emb[JIDX(i) * TT + lane] * L2E);
    #pragma unroll
    for (int i = 0; i < 4; i++) raw[i] = emb[JIDX(4 + i) * TT + lane];

    int s = 0;
    while (s + 4 <= n) {
        float nraw[4], en[4];
        #pragma unroll
        for (int i = 0; i < 4; i++) nraw[i] = emb[JIDX(s + 8 + i) * TT + lane];
        #pragma unroll
        for (int i = 0; i < 4; i++) en[i] = ex2f_(raw[i] * L2E);

        STEP(e[0] * sc);                      // even: applies pending scale
        STEP(e[1]);
        extract_scale(pcur, Kacc, pend, sc);
        STEP(e[2] * sc);
        STEP(e[3]);
        extract_scale(pcur, Kacc, pend, sc);

        #pragma unroll
        for (int i = 0; i < 4; i++) { e[i] = en[i]; raw[i] = nraw[i]; }
        s += 4;
    }
    #pragma unroll
    for (int k = 0; k < 4; k++) {
        if (s < n) {
            STEP(e[k] * sc);
            extract_scale(pcur, Kacc, pend, sc);
            s++;
        }
    }
    #undef STEP
    #undef JIDX
}

__global__ void __launch_bounds__(THREADS)
crf_fused_kernel(const float* __restrict__ em,
                 const int* __restrict__ tags,
                 const void* __restrict__ maskp,
                 const float* __restrict__ startv,
                 const float* __restrict__ transv,
                 const float* __restrict__ endv,
                 float* __restrict__ out)
{
    __shared__ float s_trans[TT * TT];
    __shared__ float s_start[TT];
    __shared__ float s_end[TT];
    __shared__ __align__(16) float s_p[NWARP][2][TT];   // per-warp p double buffer
    __shared__ __align__(16) float s_bm[BPB][TT];       // B_mid from backward warp
    __shared__ double s_nb[BPB];                        // backward numerator partial
    __shared__ int    s_kb[BPB];                        // backward Kacc
    __shared__ double s_r1[NWARP], s_r2[NWARP];
    __shared__ bool   s_last;

    const int  tid   = threadIdx.x;
    const int  w     = tid >> 5;
    const int  lane  = tid & 31;
    const bool isF   = (w < BPB);
    const int  slot  = isF ? w : (w - BPB);
    const int  b     = blockIdx.x * BPB + slot;
    const int  qbase = (lane >> 3) << 3;

    for (int i = tid; i < TT * TT; i += THREADS) s_trans[i] = transv[i];
    if (tid < TT) { s_start[tid] = startv[tid]; s_end[tid] = endv[tid]; }
    __syncthreads();

    const float L2E = 1.4426950408889634f;

    int head = 0, tail = -1, len = 0;
    if (b < BATCH) {
        const int mmode = probe_mask_mode(maskp);
        const size_t mbase = (size_t)b * SLEN;
        int h = -1;
        #pragma unroll 4
        for (int i = 0; i < SLEN / 32; i++) {
            bool mv = mask_at(maskp, mmode, mbase + i * 32 + lane);
            unsigned bits = __ballot_sync(FULLM, mv);
            len += __popc(bits);
            if (bits) {
                if (h < 0) h = i * 32 + (__ffs(bits) - 1);
                tail = i * 32 + 31 - __clz(bits);
            }
        }
        head = (h < 0) ? 0 : h;
    }

    const bool active = (b < BATCH) && (len > 0);
    float  pF = 0.0f;
    int    KaccF = 0;
    double nsumF = 0.0;

    if (active) {
        const float* emb = em + (size_t)b * SLEN * TT;
        const int*   tg  = tags + (size_t)b * SLEN;
        const int    mid  = (head + tail) >> 1;
        const bool   hasB = (tail > mid);

        if (isF) {
            // ---------- FORWARD WARP ----------
            double nsum = 0.0;
            #pragma unroll 4
            for (int j = head + 1 + lane; j <= mid; j += 32) {
                int tj = tg[j], tp = tg[j - 1];
                nsum += (double)s_trans[tp * TT + tj] + (double)emb[j * TT + tj];
            }
            #pragma unroll
            for (int o = 16; o; o >>= 1) nsum += __shfl_xor_sync(FULLM, nsum, o);
            int th = tg[head], tl = tg[tail];
            nsumF = nsum + (double)s_start[th] + (double)emb[head * TT + th] + (double)s_end[tl];

            // E (fwd): E[4j+i] = (e^trans[t0][c_j], e^trans[t0+1][c_j])
            unsigned long long E[16];
            #pragma unroll
            for (int jj = 0; jj < 4; jj++) {
                int c = lane ^ (jj << 3);
                #pragma unroll
                for (int i = 0; i < 4; i++) {
                    int t0 = qbase + 2 * i;
                    E[4 * jj + i] = pk2(expf(s_trans[t0 * TT + c]),
                                        expf(s_trans[(t0 + 1) * TT + c]));
                }
            }

            // init at head: raw exp2 of (start+em), no normalization
            pF = exp2f((s_start[lane] + emb[head * TT + lane]) * L2E);
            int par = 0;
            s_p[w][0][lane] = pF;
            float sc = 1.0f; int pend = 0;
            run_chain<1>(emb, head + 1, mid - head, lane, qbase, E, s_p[w], par,
                         pF, sc, KaccF, pend);
            // drop final pend (its sc never applied)
        } else {
            // ---------- BACKWARD WARP ----------
            double nsum = 0.0;
            #pragma unroll 4
            for (int j = mid + 1 + lane; j <= tail; j += 32) {
                int tj = tg[j], tp = tg[j - 1];
                nsum += (double)s_trans[tp * TT + tj] + (double)emb[j * TT + tj];
            }
            #pragma unroll
            for (int o = 16; o; o >>= 1) nsum += __shfl_xor_sync(FULLM, nsum, o);
            if (lane == 0) s_nb[slot] = nsum;

            // E^T (bwd): E[4j+i] = (e^trans[c_j][t0], e^trans[c_j][t0+1])
            unsigned long long E[16];
            #pragma unroll
            for (int jj = 0; jj < 4; jj++) {
                int c = lane ^ (jj << 3);
                #pragma unroll
                for (int i = 0; i < 4; i++) {
                    int t0 = qbase + 2 * i;
                    E[4 * jj + i] = pk2(expf(s_trans[c * TT + t0]),
                                        expf(s_trans[c * TT + t0 + 1]));
                }
            }

            float bm;
            int   KaccB = 0;
            if (hasB) {
                float pB = ex2f_(emb[tail * TT + lane] * L2E) * expf(s_end[lane]);
                int pend;
                float sc;
                {   // initial extraction
                    float p0 = __shfl_sync(FULLM, pB, 0);
                    int e = __float_as_int(p0) >> 23;
                    pend = e - 127;
                    sc = __int_as_float((254 - e) << 23);
                }
                int par = 0;
                s_p[w][0][lane] = pB;
                run_chain<-1>(emb, tail - 1, tail - mid - 1, lane, qbase, E, s_p[w], par,
                              pB, sc, KaccB, pend);
                // final dot (no emission): consumes pending sc
                bm = dot_smem(s_p[w][par], qbase, E) * sc;
                KaccB += pend;
            } else {
                bm = expf(s_end[lane]);
            }
            s_bm[slot][lane] = bm;
            if (lane == 0) s_kb[slot] = KaccB;
        }
    } else if (b < BATCH && isF && lane == 0) {
        g_contrib[b] = 0.0; g_cnt[b] = 0.0;
    }

    __syncthreads();   // backward results (s_bm, s_nb, s_kb) visible

    if (active && isF) {
        float vv = pF * s_bm[slot][lane];
        #pragma unroll
        for (int o = 16; o; o >>= 1) vv += __shfl_xor_sync(FULLM, vv, o);
        const double LN2 = 0.6931471805599453;
        double denom = ((double)KaccF + (double)s_kb[slot] + (double)log2f(vv)) * LN2;
        double num   = nsumF + s_nb[slot];
        if (lane == 0) {
            g_contrib[b] = (denom - num) / ((double)len + 1e-6);
            g_cnt[b]     = 1.0;
        }
    }

    // ---- last-block-done fused reduction (deterministic fixed order) ----
    __syncthreads();
    if (tid == 0) {
        __threadfence();
        s_last = (atomicAdd(&g_sem, 1u) == (unsigned)(gridDim.x - 1));
    }
    __syncthreads();
    if (s_last) {
        __threadfence();
        double a = 0.0, c = 0.0;
        for (int i = tid; i < BATCH; i += THREADS) { a += g_contrib[i]; c += g_cnt[i]; }
        #pragma unroll
        for (int o = 16; o; o >>= 1) {
            a += __shfl_xor_sync(FULLM, a, o);
            c += __shfl_xor_sync(FULLM, c, o);
        }
        if (lane == 0) { s_r1[w] = a; s_r2[w] = c; }
        __syncthreads();
        if (tid == 0) {
            double A = 0.0, C = 0.0;
            for (int i = 0; i < NWARP; i++) { A += s_r1[i]; C += s_r2[i]; }
            out[0] = (float)(A / (C + 1e-6));
            g_sem = 0;   // re-arm for next graph replay
        }
    }
}

extern "C" void kernel_launch(void* const* d_in, const int* in_sizes, int n_in,
                              void* d_out, int out_size)
{
    const float* em    = (const float*)d_in[0];
    const int*   tags  = (const int*)d_in[1];
    const void*  mask  = (const void*)d_in[2];
    const float* st    = (const float*)d_in[3];
    const float* tr    = (const float*)d_in[4];
    const float* en    = (const float*)d_in[5];

    crf_fused_kernel<<<NBLK, THREADS>>>(em, tags, mask, st, tr, en, (float*)d_out);
}